// round 1
// baseline (speedup 1.0000x reference)
#include <cuda_runtime.h>
#include <math.h>

#define Bb 2
#define Ss 2048
#define Hh 2048
#define NHh 16
#define HDd 128
#define Mm (Bb*Ss)

// ---------------- scratch (static device globals; no allocations) ----------------
__device__ float g_q[(size_t)Bb*NHh*Ss*HDd];
__device__ float g_k[(size_t)Bb*NHh*Ss*HDd];
__device__ float g_v[(size_t)Bb*NHh*Ss*HDd];
__device__ float g_o[(size_t)Bb*Ss*Hh];
__device__ float g_cos[Ss*64];
__device__ float g_sin[Ss*64];

// ---------------- GEMM: C = A(M,K) * W^T  (W is (N,K) row-major) ----------------
// MODE 0: C row-major [M,N].  MODE 1: scatter to [B,NH,S,HD] head layout.
template <int MODE>
__global__ __launch_bounds__(256) void gemm_nt(const float* __restrict__ A,
                                               const float* __restrict__ W,
                                               float* __restrict__ C,
                                               int Mn, int Nn, int Kn)
{
    __shared__ float As[8][132];
    __shared__ float Bs[8][132];

    const int tid = threadIdx.x;
    const int m0 = blockIdx.y * 128;
    const int n0 = blockIdx.x * 128;
    const int ty = tid >> 4;       // 0..15
    const int tx = tid & 15;       // 0..15
    const int lr = tid >> 1;       // 0..127
    const int lc = (tid & 1) * 4;  // 0 or 4

    const float* Ap = A + (size_t)(m0 + lr) * Kn + lc;
    const float* Wp = W + (size_t)(n0 + lr) * Kn + lc;

    float acc[8][8];
#pragma unroll
    for (int i = 0; i < 8; i++)
#pragma unroll
        for (int j = 0; j < 8; j++) acc[i][j] = 0.f;

    for (int k0 = 0; k0 < Kn; k0 += 8) {
        float4 av = *(const float4*)(Ap + k0);
        float4 bv = *(const float4*)(Wp + k0);
        __syncthreads();
        As[lc + 0][lr] = av.x; As[lc + 1][lr] = av.y;
        As[lc + 2][lr] = av.z; As[lc + 3][lr] = av.w;
        Bs[lc + 0][lr] = bv.x; Bs[lc + 1][lr] = bv.y;
        Bs[lc + 2][lr] = bv.z; Bs[lc + 3][lr] = bv.w;
        __syncthreads();
#pragma unroll
        for (int kk = 0; kk < 8; kk++) {
            float a[8], b[8];
#pragma unroll
            for (int i = 0; i < 8; i++) a[i] = As[kk][ty + 16 * i];
#pragma unroll
            for (int j = 0; j < 8; j++) b[j] = Bs[kk][tx + 16 * j];
#pragma unroll
            for (int i = 0; i < 8; i++)
#pragma unroll
                for (int j = 0; j < 8; j++)
                    acc[i][j] = fmaf(a[i], b[j], acc[i][j]);
        }
    }

#pragma unroll
    for (int i = 0; i < 8; i++) {
        const int m = m0 + ty + 16 * i;
#pragma unroll
        for (int j = 0; j < 8; j++) {
            const int n = n0 + tx + 16 * j;
            const float v = acc[i][j];
            if (MODE == 0) {
                C[(size_t)m * Nn + n] = v;
            } else {
                const int b_ = m >> 11;          // m / S
                const int s_ = m & (Ss - 1);
                const int h_ = n >> 7;           // n / HD
                const int d_ = n & (HDd - 1);
                C[(((size_t)b_ * NHh + h_) * Ss + s_) * HDd + d_] = v;
            }
        }
    }
}

// ---------------- RoPE tables: cos/sin(s * theta^(-d/64)) ----------------
__global__ void rope_tables_kernel()
{
    int idx = blockIdx.x * blockDim.x + threadIdx.x;
    if (idx >= Ss * 64) return;
    int s = idx >> 6;
    int d = idx & 63;
    float invf = (float)pow(10000.0, -(double)d * (1.0 / 64.0));  // correctly rounded
    float ang = (float)s * invf;                                   // fp32 mul, matches ref
    float c, sn;
    sincosf(ang, &sn, &c);
    g_cos[idx] = c;
    g_sin[idx] = sn;
}

// ---------------- RoPE apply (in place on Q,K) ----------------
__global__ void rope_apply_kernel(float* __restrict__ q, float* __restrict__ k)
{
    int idx = blockIdx.x * blockDim.x + threadIdx.x;  // B*NH*S*64 threads
    if (idx >= Bb * NHh * Ss * 64) return;
    const int d = idx & 63;
    const int s = (idx >> 6) & (Ss - 1);
    const int bh = idx >> 17;  // 64*2048 = 2^17
    const int t = (s << 6) + d;
    const float c = g_cos[t];
    const float sn = g_sin[t];
    const size_t base = ((size_t)bh * Ss + s) * HDd + d;
    float q1 = q[base], q2 = q[base + 64];
    q[base]      = q1 * c - q2 * sn;
    q[base + 64] = q2 * c + q1 * sn;
    float k1 = k[base], k2 = k[base + 64];
    k[base]      = k1 * c - k2 * sn;
    k[base + 64] = k2 * c + k1 * sn;
}

// ---------------- Causal flash attention (fp32), BM=128, BN=64 ----------------
// Q/K/V: [B,NH,S,HD]; output written to g_o in [B,S,H] layout.
__global__ __launch_bounds__(256) void flash_kernel(const float* __restrict__ Q,
                                                    const float* __restrict__ K,
                                                    const float* __restrict__ V,
                                                    float* __restrict__ O)
{
    constexpr int BM = 128, BN = 64;
    extern __shared__ float smf[];
    float* Qs = smf;                 // [128][129]  Qs[d*129 + r]   (transposed)
    float* Ks = Qs + 128 * 129;      // [64][133]   Ks[j*133 + d]
    float* Vs = Ks + 64 * 133;       // [64][132]   Vs[j*132 + d]
    float* Ps = Vs + 64 * 132;       // [128][65]   Ps[r*65  + j]

    const int tid = threadIdx.x;
    const int qb = blockIdx.x;
    const int bh = blockIdx.y;
    const int b = bh >> 4, h = bh & 15;
    const int qlo = qb * BM;

    const float* Qg = Q + ((size_t)bh * Ss + qlo) * HDd;
    const float* Kg = K + (size_t)bh * Ss * HDd;
    const float* Vg = V + (size_t)bh * Ss * HDd;

    // load Q block transposed
    for (int t = tid; t < BM * HDd / 4; t += 256) {
        int r = t >> 5;
        int d4 = (t & 31) << 2;
        float4 v = *(const float4*)(Qg + (size_t)r * HDd + d4);
        Qs[(d4 + 0) * 129 + r] = v.x;
        Qs[(d4 + 1) * 129 + r] = v.y;
        Qs[(d4 + 2) * 129 + r] = v.z;
        Qs[(d4 + 3) * 129 + r] = v.w;
    }

    const int ty = tid >> 4;
    const int tx = tid & 15;
    const int r0 = ty * 8;   // row group (8 rows)
    const int c0 = tx * 4;   // score cols (4 of 64)
    const int d0 = tx * 8;   // output cols (8 of 128)

    float m_i[8], l_i[8], o_acc[8][8];
#pragma unroll
    for (int i = 0; i < 8; i++) {
        m_i[i] = -1e30f;
        l_i[i] = 0.f;
#pragma unroll
        for (int c = 0; c < 8; c++) o_acc[i][c] = 0.f;
    }

    const float rscale = 0.08838834764831845f;  // 1/sqrt(128)
    const int nkb = 2 * qb + 2;

    for (int kb = 0; kb < nkb; kb++) {
        const int klo = kb * BN;
        __syncthreads();
        // load K/V tiles
        for (int t = tid; t < BN * HDd / 4; t += 256) {
            int j = t >> 5;
            int d4 = (t & 31) << 2;
            float4 kv = *(const float4*)(Kg + (size_t)(klo + j) * HDd + d4);
            Ks[j * 133 + d4 + 0] = kv.x;
            Ks[j * 133 + d4 + 1] = kv.y;
            Ks[j * 133 + d4 + 2] = kv.z;
            Ks[j * 133 + d4 + 3] = kv.w;
            float4 vv = *(const float4*)(Vg + (size_t)(klo + j) * HDd + d4);
            *(float4*)(Vs + j * 132 + d4) = vv;
        }
        __syncthreads();

        // S = Q K^T  (8x4 per thread)
        float sc[8][4];
#pragma unroll
        for (int i = 0; i < 8; i++)
#pragma unroll
            for (int j = 0; j < 4; j++) sc[i][j] = 0.f;

#pragma unroll 2
        for (int d = 0; d < HDd; d++) {
            float a[8], bb[4];
#pragma unroll
            for (int i = 0; i < 8; i++) a[i] = Qs[d * 129 + r0 + i];
#pragma unroll
            for (int j = 0; j < 4; j++) bb[j] = Ks[(c0 + j) * 133 + d];
#pragma unroll
            for (int i = 0; i < 8; i++)
#pragma unroll
                for (int j = 0; j < 4; j++)
                    sc[i][j] = fmaf(a[i], bb[j], sc[i][j]);
        }

        const bool need_mask = (kb >= 2 * qb);
#pragma unroll
        for (int i = 0; i < 8; i++)
#pragma unroll
            for (int j = 0; j < 4; j++) {
                float v = sc[i][j] * rscale;
                if (need_mask && (klo + c0 + j > qlo + r0 + i)) v = -1e30f;
                sc[i][j] = v;
            }

        // row max across the 16 threads of this row group
        float mn[8];
#pragma unroll
        for (int i = 0; i < 8; i++) {
            float v = fmaxf(fmaxf(sc[i][0], sc[i][1]), fmaxf(sc[i][2], sc[i][3]));
#pragma unroll
            for (int off = 8; off > 0; off >>= 1)
                v = fmaxf(v, __shfl_xor_sync(0xffffffffu, v, off));
            mn[i] = v;
        }

        float alpha[8];
#pragma unroll
        for (int i = 0; i < 8; i++) {
            float mt = fmaxf(m_i[i], mn[i]);
            alpha[i] = expf(m_i[i] - mt);
            m_i[i] = mt;
        }

        // probabilities + row sums
        float ls[8];
#pragma unroll
        for (int i = 0; i < 8; i++) {
            float t = 0.f;
#pragma unroll
            for (int j = 0; j < 4; j++) {
                float p = expf(sc[i][j] - m_i[i]);
                Ps[(r0 + i) * 65 + c0 + j] = p;
                t += p;
            }
#pragma unroll
            for (int off = 8; off > 0; off >>= 1)
                t += __shfl_xor_sync(0xffffffffu, t, off);
            ls[i] = t;
        }

#pragma unroll
        for (int i = 0; i < 8; i++) {
            l_i[i] = l_i[i] * alpha[i] + ls[i];
#pragma unroll
            for (int c = 0; c < 8; c++) o_acc[i][c] *= alpha[i];
        }
        __syncthreads();

        // O += P V  (8x8 per thread)
#pragma unroll 2
        for (int j = 0; j < BN; j++) {
            float pc[8], vr[8];
#pragma unroll
            for (int i = 0; i < 8; i++) pc[i] = Ps[(r0 + i) * 65 + j];
#pragma unroll
            for (int c = 0; c < 8; c++) vr[c] = Vs[j * 132 + d0 + c];
#pragma unroll
            for (int i = 0; i < 8; i++)
#pragma unroll
                for (int c = 0; c < 8; c++)
                    o_acc[i][c] = fmaf(pc[i], vr[c], o_acc[i][c]);
        }
    }

    // epilogue: normalize, write [B,S,H]
#pragma unroll
    for (int i = 0; i < 8; i++) {
        const int qrow = qlo + r0 + i;
        const float inv = 1.f / l_i[i];
        const size_t base = ((size_t)b * Ss + qrow) * Hh + h * HDd + d0;
        float4 v0 = make_float4(o_acc[i][0] * inv, o_acc[i][1] * inv,
                                o_acc[i][2] * inv, o_acc[i][3] * inv);
        float4 v1 = make_float4(o_acc[i][4] * inv, o_acc[i][5] * inv,
                                o_acc[i][6] * inv, o_acc[i][7] * inv);
        *(float4*)(O + base) = v0;
        *(float4*)(O + base + 4) = v1;
    }
}

// ---------------- launch ----------------
extern "C" void kernel_launch(void* const* d_in, const int* in_sizes, int n_in,
                              void* d_out, int out_size)
{
    (void)in_sizes; (void)n_in; (void)out_size;
    const float* hs = (const float*)d_in[0];
    const float* qw = (const float*)d_in[1];
    const float* kw = (const float*)d_in[2];
    const float* vw = (const float*)d_in[3];
    const float* ow = (const float*)d_in[4];
    float* out = (float*)d_out;

    float *qbuf, *kbuf, *vbuf, *obuf;
    cudaGetSymbolAddress((void**)&qbuf, g_q);
    cudaGetSymbolAddress((void**)&kbuf, g_k);
    cudaGetSymbolAddress((void**)&vbuf, g_v);
    cudaGetSymbolAddress((void**)&obuf, g_o);

    const dim3 gGemm(Hh / 128, Mm / 128);  // (16, 32)

    gemm_nt<1><<<gGemm, 256>>>(hs, qw, qbuf, Mm, Hh, Hh);
    gemm_nt<1><<<gGemm, 256>>>(hs, kw, kbuf, Mm, Hh, Hh);
    gemm_nt<1><<<gGemm, 256>>>(hs, vw, vbuf, Mm, Hh, Hh);

    rope_tables_kernel<<<(Ss * 64 + 255) / 256, 256>>>();
    rope_apply_kernel<<<(Bb * NHh * Ss * 64 + 255) / 256, 256>>>(qbuf, kbuf);

    const int flash_smem = (128 * 129 + 64 * 133 + 64 * 132 + 128 * 65) * 4;  // 167168
    cudaFuncSetAttribute(flash_kernel, cudaFuncAttributeMaxDynamicSharedMemorySize,
                         flash_smem);
    flash_kernel<<<dim3(Ss / 128, Bb * NHh), 256, flash_smem>>>(qbuf, kbuf, vbuf, obuf);

    gemm_nt<0><<<gGemm, 256>>>(obuf, ow, out, Mm, Hh, Hh);
}

// round 3
// speedup vs baseline: 2.0336x; 2.0336x over previous
#include <cuda_runtime.h>
#include <cuda_bf16.h>
#include <math.h>
#include <stdint.h>

#define Bb 2
#define Ss 2048
#define Hh 2048
#define NHh 16
#define HDd 128
#define Mm (Bb*Ss)
#define K3 (3*Hh)          // 6144 (bf16x3 split along K)
#define KC 64              // bf16 per K-chunk = 128 bytes per row
#define NCHUNK (K3/KC)     // 96

// ---------------- scratch (static device globals; no allocations) ----------------
__device__ float g_q[(size_t)Bb*NHh*Ss*HDd];
__device__ float g_k[(size_t)Bb*NHh*Ss*HDd];
__device__ float g_v[(size_t)Bb*NHh*Ss*HDd];
__device__ float g_o[(size_t)Bb*Ss*Hh];
__device__ float g_cos[Ss*64];
__device__ float g_sin[Ss*64];
__device__ __nv_bfloat16 g_a3[(size_t)Mm*K3];   // split activations [M, 3K]
__device__ __nv_bfloat16 g_w3[(size_t)Hh*K3];   // split weight      [N, 3K]

// ---------------- PTX helpers (all plain-sm_103-safe: sm_80/75 features) --------
__device__ __forceinline__ uint32_t smem_u32(const void* p) {
    uint32_t a;
    asm("{ .reg .u64 t; cvta.to.shared.u64 t, %1; cvt.u32.u64 %0, t; }" : "=r"(a) : "l"(p));
    return a;
}
#define CP_ASYNC16(sa, gp) \
    asm volatile("cp.async.cg.shared.global [%0], [%1], 16;" :: "r"(sa), "l"(gp) : "memory")
#define CP_COMMIT() asm volatile("cp.async.commit_group;" ::: "memory")
#define CP_WAIT0()  asm volatile("cp.async.wait_group 0;" ::: "memory")
#define CP_WAIT1()  asm volatile("cp.async.wait_group 1;" ::: "memory")

__device__ __forceinline__ void ldsm_x4(uint32_t* r, uint32_t addr) {
    asm volatile("ldmatrix.sync.aligned.m8n8.x4.shared.b16 {%0,%1,%2,%3}, [%4];"
        : "=r"(r[0]), "=r"(r[1]), "=r"(r[2]), "=r"(r[3]) : "r"(addr));
}
__device__ __forceinline__ void ldsm_x2(uint32_t* r, uint32_t addr) {
    asm volatile("ldmatrix.sync.aligned.m8n8.x2.shared.b16 {%0,%1}, [%2];"
        : "=r"(r[0]), "=r"(r[1]) : "r"(addr));
}
__device__ __forceinline__ void mma16816(float* d, const uint32_t* a, const uint32_t* b) {
    asm volatile("mma.sync.aligned.m16n8k16.row.col.f32.bf16.bf16.f32 "
        "{%0,%1,%2,%3}, {%4,%5,%6,%7}, {%8,%9}, {%0,%1,%2,%3};"
        : "+f"(d[0]), "+f"(d[1]), "+f"(d[2]), "+f"(d[3])
        : "r"(a[0]), "r"(a[1]), "r"(a[2]), "r"(a[3]), "r"(b[0]), "r"(b[1]));
}

// swizzle helper for cp.async stores: full byte-offset swizzle within 1KB atom
#define SWZ(off) ((off) ^ (((off) >> 3) & 0x70))

// ---------------- split fp32 -> bf16x3 along K ----------------
// order 0 (activations): [hi, lo, hi];  order 1 (weights): [hi, hi, lo]
// product sum over K3 = hi*hi + lo*hi + hi*lo  (drops lo*lo ~ 2^-18 rel)
__global__ void split_kernel(const float* __restrict__ X, __nv_bfloat16* __restrict__ Y,
                             int total, int order)
{
    int idx = blockIdx.x * blockDim.x + threadIdx.x;
    if (idx >= total) return;
    const int r = idx >> 11;          // K = 2048
    const int k = idx & 2047;
    const float x = X[idx];
    const __nv_bfloat16 hi = __float2bfloat16(x);
    const __nv_bfloat16 lo = __float2bfloat16(x - __bfloat162float(hi));
    const size_t base = (size_t)r * K3 + k;
    Y[base] = hi;
    Y[base + Hh]     = order ? hi : lo;
    Y[base + 2 * Hh] = order ? lo : hi;
}

// ---------------- HMMA GEMM: C[M,N] = A'[M,3K] * B'[N,3K]^T ----------------
// MODE 0: C row-major [M,N].  MODE 1: scatter to [B,NH,S,HD].
template <int MODE>
__global__ __launch_bounds__(256, 2) void gemm_mma(const __nv_bfloat16* __restrict__ A,
                                                   const __nv_bfloat16* __restrict__ Bw,
                                                   float* __restrict__ C)
{
    extern __shared__ char smem[];
    const uint32_t sb = smem_u32(smem);
    const int tid = threadIdx.x;
    const int wid = tid >> 5;
    const int lane = tid & 31;
    const int n0 = blockIdx.x * 128;
    const int m0 = blockIdx.y * 128;

    const uint32_t offA0 = 0u,     offA1 = 16384u;
    const uint32_t offB0 = 32768u, offB1 = 49152u;

    const int wm = wid & 1;      // 0..1  -> 64 rows
    const int wn = wid >> 1;     // 0..3  -> 32 cols

    float acc[4][4][4];
#pragma unroll
    for (int mi = 0; mi < 4; mi++)
#pragma unroll
        for (int ni = 0; ni < 4; ni++)
#pragma unroll
            for (int q = 0; q < 4; q++) acc[mi][ni][q] = 0.f;

    // cp.async load pattern: thread t -> row t>>3 (+32*i), bytes (t&7)*16
    const int r_ld = tid >> 3;
    const int c_ld = (tid & 7) * 16;

#define LOAD_CHUNK(cidx, offa, offb) do {                                          \
    const int _k0 = (cidx) * KC;                                                   \
    _Pragma("unroll")                                                              \
    for (int _i = 0; _i < 4; _i++) {                                               \
        const int _r = r_ld + _i * 32;                                             \
        const __nv_bfloat16* _gp = A + (size_t)(m0 + _r) * K3 + _k0 + (c_ld >> 1); \
        CP_ASYNC16(sb + (offa) + SWZ(_r * 128 + c_ld), _gp);                       \
    }                                                                              \
    _Pragma("unroll")                                                              \
    for (int _i = 0; _i < 4; _i++) {                                               \
        const int _r = r_ld + _i * 32;                                             \
        const __nv_bfloat16* _gp = Bw + (size_t)(n0 + _r) * K3 + _k0 + (c_ld >> 1);\
        CP_ASYNC16(sb + (offb) + SWZ(_r * 128 + c_ld), _gp);                       \
    }                                                                              \
    CP_COMMIT();                                                                   \
} while (0)

    // ldmatrix per-thread address components.
    // For row r in a 128B-pitch swizzled tile: addr = base + r*128 + (col ^ ((r&7)*16))
    const int a_lrow = lane & 15;            // row within 16-row ldmatrix block
    const int a_colb = (lane >> 4) * 16;     // 0 or 16 (k0 / k8 halves)
    const int a_xor = (a_lrow & 7) * 16;
    uint32_t aRow[4];
#pragma unroll
    for (int mi = 0; mi < 4; mi++)
        aRow[mi] = (uint32_t)((wm * 64 + mi * 16 + a_lrow) * 128);

    const int b_lrow = lane & 7;
    const int b_colb = ((lane >> 3) & 1) * 16;
    const int b_xor = (b_lrow & 7) * 16;
    uint32_t bRow[4];
#pragma unroll
    for (int ni = 0; ni < 4; ni++)
        bRow[ni] = (uint32_t)((wn * 32 + ni * 8 + b_lrow) * 128);

    LOAD_CHUNK(0, offA0, offB0);

    for (int c = 0; c < NCHUNK; c++) {
        const int s = c & 1;
        if (c + 1 < NCHUNK) {
            if (s == 0) LOAD_CHUNK(c + 1, offA1, offB1);
            else        LOAD_CHUNK(c + 1, offA0, offB0);
            CP_WAIT1();
        } else {
            CP_WAIT0();
        }
        __syncthreads();

        const uint32_t ab = sb + (s ? offA1 : offB0 - 32768u + offA1 - 16384u); // = offA1 or offA0
        const uint32_t ab2 = sb + (s ? offA1 : offA0);
        const uint32_t bb2 = sb + (s ? offB1 : offB0);
        (void)ab;

#pragma unroll
        for (int kk = 0; kk < 4; kk++) {
            const uint32_t acol = (uint32_t)(kk * 32 + a_colb) ^ (uint32_t)a_xor;
            const uint32_t bcol = (uint32_t)(kk * 32 + b_colb) ^ (uint32_t)b_xor;
            uint32_t afr[4][4], bfr[4][2];
#pragma unroll
            for (int mi = 0; mi < 4; mi++)
                ldsm_x4(afr[mi], ab2 + aRow[mi] + acol);
#pragma unroll
            for (int ni = 0; ni < 4; ni++)
                ldsm_x2(bfr[ni], bb2 + bRow[ni] + bcol);
#pragma unroll
            for (int mi = 0; mi < 4; mi++)
#pragma unroll
                for (int ni = 0; ni < 4; ni++)
                    mma16816(acc[mi][ni], afr[mi], bfr[ni]);
        }
        __syncthreads();
    }

    // epilogue: thread owns rows (t/4, t/4+8), cols 2*(t%4)..+1 of each 16x8 tile
    const int er = lane >> 2;
    const int ec = (lane & 3) * 2;
#pragma unroll
    for (int mi = 0; mi < 4; mi++) {
#pragma unroll
        for (int ni = 0; ni < 4; ni++) {
            const int m = m0 + wm * 64 + mi * 16 + er;
            const int n = n0 + wn * 32 + ni * 8 + ec;
            float* dst0;
            float* dst1;
            if (MODE == 0) {
                dst0 = C + (size_t)m * Hh + n;
                dst1 = C + (size_t)(m + 8) * Hh + n;
            } else {
                const int b_ = m >> 11;
                const int s_ = m & (Ss - 1);
                const int h_ = n >> 7;
                const int d_ = n & (HDd - 1);
                dst0 = C + (((size_t)b_ * NHh + h_) * Ss + s_) * HDd + d_;
                dst1 = dst0 + 8 * HDd;   // m+8 -> s_+8, same head
            }
            *(float2*)dst0 = make_float2(acc[mi][ni][0], acc[mi][ni][1]);
            *(float2*)dst1 = make_float2(acc[mi][ni][2], acc[mi][ni][3]);
        }
    }
#undef LOAD_CHUNK
}

// ---------------- RoPE tables ----------------
__global__ void rope_tables_kernel()
{
    int idx = blockIdx.x * blockDim.x + threadIdx.x;
    if (idx >= Ss * 64) return;
    int s = idx >> 6;
    int d = idx & 63;
    float invf = (float)pow(10000.0, -(double)d * (1.0 / 64.0));
    float ang = (float)s * invf;
    float c, sn;
    sincosf(ang, &sn, &c);
    g_cos[idx] = c;
    g_sin[idx] = sn;
}

// ---------------- RoPE apply (in place on Q,K) ----------------
__global__ void rope_apply_kernel(float* __restrict__ q, float* __restrict__ k)
{
    int idx = blockIdx.x * blockDim.x + threadIdx.x;
    if (idx >= Bb * NHh * Ss * 64) return;
    const int d = idx & 63;
    const int s = (idx >> 6) & (Ss - 1);
    const int bh = idx >> 17;
    const int t = (s << 6) + d;
    const float c = g_cos[t];
    const float sn = g_sin[t];
    const size_t base = ((size_t)bh * Ss + s) * HDd + d;
    float q1 = q[base], q2 = q[base + 64];
    q[base]      = q1 * c - q2 * sn;
    q[base + 64] = q2 * c + q1 * sn;
    float k1 = k[base], k2 = k[base + 64];
    k[base]      = k1 * c - k2 * sn;
    k[base + 64] = k2 * c + k1 * sn;
}

// ---------------- Causal flash attention (fp32), BM=128, BN=64 ----------------
__global__ __launch_bounds__(256) void flash_kernel(const float* __restrict__ Q,
                                                    const float* __restrict__ K,
                                                    const float* __restrict__ V,
                                                    float* __restrict__ O)
{
    constexpr int BM = 128, BN = 64;
    extern __shared__ float smf[];
    float* Qs = smf;                 // [128][129] transposed
    float* Ks = Qs + 128 * 129;      // [64][133]
    float* Vs = Ks + 64 * 133;       // [64][132]
    float* Ps = Vs + 64 * 132;       // [128][65]

    const int tid = threadIdx.x;
    const int qb = blockIdx.x;
    const int bh = blockIdx.y;
    const int b = bh >> 4, h = bh & 15;
    const int qlo = qb * BM;

    const float* Qg = Q + ((size_t)bh * Ss + qlo) * HDd;
    const float* Kg = K + (size_t)bh * Ss * HDd;
    const float* Vg = V + (size_t)bh * Ss * HDd;

    for (int t = tid; t < BM * HDd / 4; t += 256) {
        int r = t >> 5;
        int d4 = (t & 31) << 2;
        float4 v = *(const float4*)(Qg + (size_t)r * HDd + d4);
        Qs[(d4 + 0) * 129 + r] = v.x;
        Qs[(d4 + 1) * 129 + r] = v.y;
        Qs[(d4 + 2) * 129 + r] = v.z;
        Qs[(d4 + 3) * 129 + r] = v.w;
    }

    const int ty = tid >> 4;
    const int tx = tid & 15;
    const int r0 = ty * 8;
    const int c0 = tx * 4;
    const int d0 = tx * 8;

    float m_i[8], l_i[8], o_acc[8][8];
#pragma unroll
    for (int i = 0; i < 8; i++) {
        m_i[i] = -1e30f;
        l_i[i] = 0.f;
#pragma unroll
        for (int c = 0; c < 8; c++) o_acc[i][c] = 0.f;
    }

    const float rscale = 0.08838834764831845f;
    const int nkb = 2 * qb + 2;

    for (int kb = 0; kb < nkb; kb++) {
        const int klo = kb * BN;
        __syncthreads();
        for (int t = tid; t < BN * HDd / 4; t += 256) {
            int j = t >> 5;
            int d4 = (t & 31) << 2;
            float4 kv = *(const float4*)(Kg + (size_t)(klo + j) * HDd + d4);
            Ks[j * 133 + d4 + 0] = kv.x;
            Ks[j * 133 + d4 + 1] = kv.y;
            Ks[j * 133 + d4 + 2] = kv.z;
            Ks[j * 133 + d4 + 3] = kv.w;
            float4 vv = *(const float4*)(Vg + (size_t)(klo + j) * HDd + d4);
            *(float4*)(Vs + j * 132 + d4) = vv;
        }
        __syncthreads();

        float sc[8][4];
#pragma unroll
        for (int i = 0; i < 8; i++)
#pragma unroll
            for (int j = 0; j < 4; j++) sc[i][j] = 0.f;

#pragma unroll 2
        for (int d = 0; d < HDd; d++) {
            float a[8], bb[4];
#pragma unroll
            for (int i = 0; i < 8; i++) a[i] = Qs[d * 129 + r0 + i];
#pragma unroll
            for (int j = 0; j < 4; j++) bb[j] = Ks[(c0 + j) * 133 + d];
#pragma unroll
            for (int i = 0; i < 8; i++)
#pragma unroll
                for (int j = 0; j < 4; j++)
                    sc[i][j] = fmaf(a[i], bb[j], sc[i][j]);
        }

        const bool need_mask = (kb >= 2 * qb);
#pragma unroll
        for (int i = 0; i < 8; i++)
#pragma unroll
            for (int j = 0; j < 4; j++) {
                float v = sc[i][j] * rscale;
                if (need_mask && (klo + c0 + j > qlo + r0 + i)) v = -1e30f;
                sc[i][j] = v;
            }

        float mn[8];
#pragma unroll
        for (int i = 0; i < 8; i++) {
            float v = fmaxf(fmaxf(sc[i][0], sc[i][1]), fmaxf(sc[i][2], sc[i][3]));
#pragma unroll
            for (int off = 8; off > 0; off >>= 1)
                v = fmaxf(v, __shfl_xor_sync(0xffffffffu, v, off));
            mn[i] = v;
        }

        float alpha[8];
#pragma unroll
        for (int i = 0; i < 8; i++) {
            float mt = fmaxf(m_i[i], mn[i]);
            alpha[i] = expf(m_i[i] - mt);
            m_i[i] = mt;
        }

        float ls[8];
#pragma unroll
        for (int i = 0; i < 8; i++) {
            float t = 0.f;
#pragma unroll
            for (int j = 0; j < 4; j++) {
                float p = expf(sc[i][j] - m_i[i]);
                Ps[(r0 + i) * 65 + c0 + j] = p;
                t += p;
            }
#pragma unroll
            for (int off = 8; off > 0; off >>= 1)
                t += __shfl_xor_sync(0xffffffffu, t, off);
            ls[i] = t;
        }

#pragma unroll
        for (int i = 0; i < 8; i++) {
            l_i[i] = l_i[i] * alpha[i] + ls[i];
#pragma unroll
            for (int c = 0; c < 8; c++) o_acc[i][c] *= alpha[i];
        }
        __syncthreads();

#pragma unroll 2
        for (int j = 0; j < BN; j++) {
            float pc[8], vr[8];
#pragma unroll
            for (int i = 0; i < 8; i++) pc[i] = Ps[(r0 + i) * 65 + j];
#pragma unroll
            for (int c = 0; c < 8; c++) vr[c] = Vs[j * 132 + d0 + c];
#pragma unroll
            for (int i = 0; i < 8; i++)
#pragma unroll
                for (int c = 0; c < 8; c++)
                    o_acc[i][c] = fmaf(pc[i], vr[c], o_acc[i][c]);
        }
    }

#pragma unroll
    for (int i = 0; i < 8; i++) {
        const int qrow = qlo + r0 + i;
        const float inv = 1.f / l_i[i];
        const size_t base = ((size_t)b * Ss + qrow) * Hh + h * HDd + d0;
        float4 v0 = make_float4(o_acc[i][0] * inv, o_acc[i][1] * inv,
                                o_acc[i][2] * inv, o_acc[i][3] * inv);
        float4 v1 = make_float4(o_acc[i][4] * inv, o_acc[i][5] * inv,
                                o_acc[i][6] * inv, o_acc[i][7] * inv);
        *(float4*)(O + base) = v0;
        *(float4*)(O + base + 4) = v1;
    }
}

// ---------------- launch ----------------
extern "C" void kernel_launch(void* const* d_in, const int* in_sizes, int n_in,
                              void* d_out, int out_size)
{
    (void)in_sizes; (void)n_in; (void)out_size;
    const float* hs = (const float*)d_in[0];
    const float* qw = (const float*)d_in[1];
    const float* kw = (const float*)d_in[2];
    const float* vw = (const float*)d_in[3];
    const float* ow = (const float*)d_in[4];
    float* out = (float*)d_out;

    float *qbuf, *kbuf, *vbuf, *obuf;
    __nv_bfloat16 *a3, *w3;
    cudaGetSymbolAddress((void**)&qbuf, g_q);
    cudaGetSymbolAddress((void**)&kbuf, g_k);
    cudaGetSymbolAddress((void**)&vbuf, g_v);
    cudaGetSymbolAddress((void**)&obuf, g_o);
    cudaGetSymbolAddress((void**)&a3, g_a3);
    cudaGetSymbolAddress((void**)&w3, g_w3);

    const int gemm_smem = 65536;
    cudaFuncSetAttribute(gemm_mma<0>, cudaFuncAttributeMaxDynamicSharedMemorySize, gemm_smem);
    cudaFuncSetAttribute(gemm_mma<1>, cudaFuncAttributeMaxDynamicSharedMemorySize, gemm_smem);

    const dim3 gGemm(Hh / 128, Mm / 128);  // (16, 32)
    const int actN = Mm * Hh;
    const int wN = Hh * Hh;

    // split hidden states once
    split_kernel<<<(actN + 255) / 256, 256>>>(hs, a3, actN, 0);

    // Q, K, V projections
    split_kernel<<<(wN + 255) / 256, 256>>>(qw, w3, wN, 1);
    gemm_mma<1><<<gGemm, 256, gemm_smem>>>(a3, w3, qbuf);
    split_kernel<<<(wN + 255) / 256, 256>>>(kw, w3, wN, 1);
    gemm_mma<1><<<gGemm, 256, gemm_smem>>>(a3, w3, kbuf);
    split_kernel<<<(wN + 255) / 256, 256>>>(vw, w3, wN, 1);
    gemm_mma<1><<<gGemm, 256, gemm_smem>>>(a3, w3, vbuf);

    rope_tables_kernel<<<(Ss * 64 + 255) / 256, 256>>>();
    rope_apply_kernel<<<(Bb * NHh * Ss * 64 + 255) / 256, 256>>>(qbuf, kbuf);

    const int flash_smem = (128 * 129 + 64 * 133 + 64 * 132 + 128 * 65) * 4;
    cudaFuncSetAttribute(flash_kernel, cudaFuncAttributeMaxDynamicSharedMemorySize,
                         flash_smem);
    flash_kernel<<<dim3(Ss / 128, Bb * NHh), 256, flash_smem>>>(qbuf, kbuf, vbuf, obuf);

    // output projection
    split_kernel<<<(actN + 255) / 256, 256>>>(obuf, a3, actN, 0);
    split_kernel<<<(wN + 255) / 256, 256>>>(ow, w3, wN, 1);
    gemm_mma<0><<<gGemm, 256, gemm_smem>>>(a3, w3, out);
}

// round 4
// speedup vs baseline: 3.5401x; 1.7408x over previous
#include <cuda_runtime.h>
#include <cuda_bf16.h>
#include <math.h>
#include <stdint.h>

#define Bb 2
#define Ss 2048
#define Hh 2048
#define NHh 16
#define HDd 128
#define Mm (Bb*Ss)
#define K3 (3*Hh)          // 6144 (bf16x3 split along K)
#define KC 64
#define NCHUNK (K3/KC)     // 96

// ---------------- scratch ----------------
__device__ float g_q[(size_t)Bb*NHh*Ss*HDd];
__device__ float g_k[(size_t)Bb*NHh*Ss*HDd];
__device__ float g_v[(size_t)Bb*NHh*Ss*HDd];
__device__ float g_o[(size_t)Bb*Ss*Hh];
__device__ float g_cos[Ss*64];
__device__ float g_sin[Ss*64];
__device__ __nv_bfloat16 g_a3[(size_t)Mm*K3];
__device__ __nv_bfloat16 g_w3[(size_t)Hh*K3];
// flash bf16 operands (hi/lo split)
__device__ __nv_bfloat16 g_qh[(size_t)Bb*NHh*Ss*HDd];
__device__ __nv_bfloat16 g_ql[(size_t)Bb*NHh*Ss*HDd];
__device__ __nv_bfloat16 g_kh[(size_t)Bb*NHh*Ss*HDd];
__device__ __nv_bfloat16 g_kl[(size_t)Bb*NHh*Ss*HDd];
__device__ __nv_bfloat16 g_vh[(size_t)Bb*NHh*Ss*HDd];
__device__ __nv_bfloat16 g_vl[(size_t)Bb*NHh*Ss*HDd];

// ---------------- PTX helpers ----------------
__device__ __forceinline__ uint32_t smem_u32(const void* p) {
    uint32_t a;
    asm("{ .reg .u64 t; cvta.to.shared.u64 t, %1; cvt.u32.u64 %0, t; }" : "=r"(a) : "l"(p));
    return a;
}
#define CP_ASYNC16(sa, gp) \
    asm volatile("cp.async.cg.shared.global [%0], [%1], 16;" :: "r"(sa), "l"(gp) : "memory")
#define CP_COMMIT() asm volatile("cp.async.commit_group;" ::: "memory")
#define CP_WAIT0()  asm volatile("cp.async.wait_group 0;" ::: "memory")
#define CP_WAIT1()  asm volatile("cp.async.wait_group 1;" ::: "memory")

__device__ __forceinline__ void ldsm_x4(uint32_t* r, uint32_t addr) {
    asm volatile("ldmatrix.sync.aligned.m8n8.x4.shared.b16 {%0,%1,%2,%3}, [%4];"
        : "=r"(r[0]), "=r"(r[1]), "=r"(r[2]), "=r"(r[3]) : "r"(addr));
}
__device__ __forceinline__ void ldsm_x4_t(uint32_t* r, uint32_t addr) {
    asm volatile("ldmatrix.sync.aligned.m8n8.x4.trans.shared.b16 {%0,%1,%2,%3}, [%4];"
        : "=r"(r[0]), "=r"(r[1]), "=r"(r[2]), "=r"(r[3]) : "r"(addr));
}
__device__ __forceinline__ void ldsm_x2(uint32_t* r, uint32_t addr) {
    asm volatile("ldmatrix.sync.aligned.m8n8.x2.shared.b16 {%0,%1}, [%2];"
        : "=r"(r[0]), "=r"(r[1]) : "r"(addr));
}
__device__ __forceinline__ void mma16816(float* d, const uint32_t* a, const uint32_t* b) {
    asm volatile("mma.sync.aligned.m16n8k16.row.col.f32.bf16.bf16.f32 "
        "{%0,%1,%2,%3}, {%4,%5,%6,%7}, {%8,%9}, {%0,%1,%2,%3};"
        : "+f"(d[0]), "+f"(d[1]), "+f"(d[2]), "+f"(d[3])
        : "r"(a[0]), "r"(a[1]), "r"(a[2]), "r"(a[3]), "r"(b[0]), "r"(b[1]));
}
#define SWZ(off) ((off) ^ (((off) >> 3) & 0x70))

// ---------------- split fp32 -> bf16x3 along K (for projections) ----------------
__global__ void split_kernel(const float* __restrict__ X, __nv_bfloat16* __restrict__ Y,
                             int total, int order)
{
    int idx = blockIdx.x * blockDim.x + threadIdx.x;
    if (idx >= total) return;
    const int r = idx >> 11;
    const int k = idx & 2047;
    const float x = X[idx];
    const __nv_bfloat16 hi = __float2bfloat16(x);
    const __nv_bfloat16 lo = __float2bfloat16(x - __bfloat162float(hi));
    const size_t base = (size_t)r * K3 + k;
    Y[base] = hi;
    Y[base + Hh]     = order ? hi : lo;
    Y[base + 2 * Hh] = order ? lo : hi;
}

// ---------------- plain hi/lo pair split (for V) ----------------
__global__ void split_pair_kernel(const float* __restrict__ X,
                                  __nv_bfloat16* __restrict__ Xh,
                                  __nv_bfloat16* __restrict__ Xl, int n)
{
    int idx = blockIdx.x * blockDim.x + threadIdx.x;
    if (idx >= n) return;
    float x = X[idx];
    __nv_bfloat16 hi = __float2bfloat16(x);
    Xh[idx] = hi;
    Xl[idx] = __float2bfloat16(x - __bfloat162float(hi));
}

// ---------------- HMMA GEMM (unchanged from R3) ----------------
template <int MODE>
__global__ __launch_bounds__(256, 2) void gemm_mma(const __nv_bfloat16* __restrict__ A,
                                                   const __nv_bfloat16* __restrict__ Bw,
                                                   float* __restrict__ C)
{
    extern __shared__ char smem[];
    const uint32_t sb = smem_u32(smem);
    const int tid = threadIdx.x;
    const int wid = tid >> 5;
    const int lane = tid & 31;
    const int n0 = blockIdx.x * 128;
    const int m0 = blockIdx.y * 128;

    const uint32_t offA0 = 0u,     offA1 = 16384u;
    const uint32_t offB0 = 32768u, offB1 = 49152u;
    const int wm = wid & 1;
    const int wn = wid >> 1;

    float acc[4][4][4];
#pragma unroll
    for (int mi = 0; mi < 4; mi++)
#pragma unroll
        for (int ni = 0; ni < 4; ni++)
#pragma unroll
            for (int q = 0; q < 4; q++) acc[mi][ni][q] = 0.f;

    const int r_ld = tid >> 3;
    const int c_ld = (tid & 7) * 16;

#define LOAD_CHUNK(cidx, offa, offb) do {                                          \
    const int _k0 = (cidx) * KC;                                                   \
    _Pragma("unroll")                                                              \
    for (int _i = 0; _i < 4; _i++) {                                               \
        const int _r = r_ld + _i * 32;                                             \
        const __nv_bfloat16* _gp = A + (size_t)(m0 + _r) * K3 + _k0 + (c_ld >> 1); \
        CP_ASYNC16(sb + (offa) + SWZ(_r * 128 + c_ld), _gp);                       \
    }                                                                              \
    _Pragma("unroll")                                                              \
    for (int _i = 0; _i < 4; _i++) {                                               \
        const int _r = r_ld + _i * 32;                                             \
        const __nv_bfloat16* _gp = Bw + (size_t)(n0 + _r) * K3 + _k0 + (c_ld >> 1);\
        CP_ASYNC16(sb + (offb) + SWZ(_r * 128 + c_ld), _gp);                       \
    }                                                                              \
    CP_COMMIT();                                                                   \
} while (0)

    const int a_lrow = lane & 15;
    const int a_colb = (lane >> 4) * 16;
    const int a_xor = (a_lrow & 7) * 16;
    uint32_t aRow[4];
#pragma unroll
    for (int mi = 0; mi < 4; mi++)
        aRow[mi] = (uint32_t)((wm * 64 + mi * 16 + a_lrow) * 128);

    const int b_lrow = lane & 7;
    const int b_colb = ((lane >> 3) & 1) * 16;
    const int b_xor = (b_lrow & 7) * 16;
    uint32_t bRow[4];
#pragma unroll
    for (int ni = 0; ni < 4; ni++)
        bRow[ni] = (uint32_t)((wn * 32 + ni * 8 + b_lrow) * 128);

    LOAD_CHUNK(0, offA0, offB0);

    for (int c = 0; c < NCHUNK; c++) {
        const int s = c & 1;
        if (c + 1 < NCHUNK) {
            if (s == 0) LOAD_CHUNK(c + 1, offA1, offB1);
            else        LOAD_CHUNK(c + 1, offA0, offB0);
            CP_WAIT1();
        } else {
            CP_WAIT0();
        }
        __syncthreads();

        const uint32_t ab2 = sb + (s ? offA1 : offA0);
        const uint32_t bb2 = sb + (s ? offB1 : offB0);

#pragma unroll
        for (int kk = 0; kk < 4; kk++) {
            const uint32_t acol = (uint32_t)(kk * 32 + a_colb) ^ (uint32_t)a_xor;
            const uint32_t bcol = (uint32_t)(kk * 32 + b_colb) ^ (uint32_t)b_xor;
            uint32_t afr[4][4], bfr[4][2];
#pragma unroll
            for (int mi = 0; mi < 4; mi++)
                ldsm_x4(afr[mi], ab2 + aRow[mi] + acol);
#pragma unroll
            for (int ni = 0; ni < 4; ni++)
                ldsm_x2(bfr[ni], bb2 + bRow[ni] + bcol);
#pragma unroll
            for (int mi = 0; mi < 4; mi++)
#pragma unroll
                for (int ni = 0; ni < 4; ni++)
                    mma16816(acc[mi][ni], afr[mi], bfr[ni]);
        }
        __syncthreads();
    }

    const int er = lane >> 2;
    const int ec = (lane & 3) * 2;
#pragma unroll
    for (int mi = 0; mi < 4; mi++) {
#pragma unroll
        for (int ni = 0; ni < 4; ni++) {
            const int m = m0 + wm * 64 + mi * 16 + er;
            const int n = n0 + wn * 32 + ni * 8 + ec;
            float* dst0;
            float* dst1;
            if (MODE == 0) {
                dst0 = C + (size_t)m * Hh + n;
                dst1 = C + (size_t)(m + 8) * Hh + n;
            } else {
                const int b_ = m >> 11;
                const int s_ = m & (Ss - 1);
                const int h_ = n >> 7;
                const int d_ = n & (HDd - 1);
                dst0 = C + (((size_t)b_ * NHh + h_) * Ss + s_) * HDd + d_;
                dst1 = dst0 + 8 * HDd;
            }
            *(float2*)dst0 = make_float2(acc[mi][ni][0], acc[mi][ni][1]);
            *(float2*)dst1 = make_float2(acc[mi][ni][2], acc[mi][ni][3]);
        }
    }
#undef LOAD_CHUNK
}

// ---------------- RoPE tables ----------------
__global__ void rope_tables_kernel()
{
    int idx = blockIdx.x * blockDim.x + threadIdx.x;
    if (idx >= Ss * 64) return;
    int s = idx >> 6;
    int d = idx & 63;
    float invf = (float)pow(10000.0, -(double)d * (1.0 / 64.0));
    float ang = (float)s * invf;
    float c, sn;
    sincosf(ang, &sn, &c);
    g_cos[idx] = c;
    g_sin[idx] = sn;
}

// ---------------- RoPE apply + bf16 hi/lo split (Q scaled by 1/sqrt(HD)) --------
__global__ void rope_split_kernel(const float* __restrict__ q, const float* __restrict__ k,
                                  __nv_bfloat16* __restrict__ qh, __nv_bfloat16* __restrict__ ql,
                                  __nv_bfloat16* __restrict__ kh, __nv_bfloat16* __restrict__ kl)
{
    int idx = blockIdx.x * blockDim.x + threadIdx.x;
    if (idx >= Bb * NHh * Ss * 64) return;
    const int d = idx & 63;
    const int s = (idx >> 6) & (Ss - 1);
    const int bh = idx >> 17;
    const int t = (s << 6) + d;
    const float c = g_cos[t];
    const float sn = g_sin[t];
    const float rscale = 0.08838834764831845f;
    const size_t base = ((size_t)bh * Ss + s) * HDd + d;

    float q1 = q[base], q2 = q[base + 64];
    float r1 = (q1 * c - q2 * sn) * rscale;
    float r2 = (q2 * c + q1 * sn) * rscale;
    __nv_bfloat16 h1 = __float2bfloat16(r1);
    __nv_bfloat16 h2 = __float2bfloat16(r2);
    qh[base] = h1; qh[base + 64] = h2;
    ql[base] = __float2bfloat16(r1 - __bfloat162float(h1));
    ql[base + 64] = __float2bfloat16(r2 - __bfloat162float(h2));

    float k1 = k[base], k2 = k[base + 64];
    float s1 = k1 * c - k2 * sn;
    float s2 = k2 * c + k1 * sn;
    __nv_bfloat16 g1 = __float2bfloat16(s1);
    __nv_bfloat16 g2 = __float2bfloat16(s2);
    kh[base] = g1; kh[base + 64] = g2;
    kl[base] = __float2bfloat16(s1 - __bfloat162float(g1));
    kl[base + 64] = __float2bfloat16(s2 - __bfloat162float(g2));
}

// ---------------- HMMA causal flash attention, BM=128, BN=64 ----------------
// smem: Qs [128 rows x 512B] (hi|lo), Ks 2x[64 x 512B], Vh 2x[64 x 256B], Vl 2x[64 x 256B]
#define QsO 0u
#define KsO 65536u
#define VhO 131072u
#define VlO 163840u
#define FLASH_SMEM 196608

__global__ __launch_bounds__(256, 1) void flash_mma(
    const __nv_bfloat16* __restrict__ qh, const __nv_bfloat16* __restrict__ ql,
    const __nv_bfloat16* __restrict__ kh, const __nv_bfloat16* __restrict__ kl,
    const __nv_bfloat16* __restrict__ vh, const __nv_bfloat16* __restrict__ vl,
    float* __restrict__ O)
{
    extern __shared__ char smem[];
    const uint32_t sb = smem_u32(smem);
    const int tid = threadIdx.x;
    const int lane = tid & 31;
    const int w = tid >> 5;
    const int qb = (gridDim.x - 1) - blockIdx.x;   // big tiles first
    const int bh = blockIdx.y;
    const int b = bh >> 4, h = bh & 15;
    const int qlo = qb * 128;
    const int wr = w * 16;

    // ---- Q tile load (hi|lo), 512B/row, swizzled per 128B chunk ----
#pragma unroll
    for (int i = 0; i < 16; i++) {
        int idx = tid + 256 * i;
        int row = idx >> 5;
        int off = (idx & 31) * 16;
        const __nv_bfloat16* src = (off < 256)
            ? qh + ((size_t)bh * Ss + qlo + row) * HDd + (off >> 1)
            : ql + ((size_t)bh * Ss + qlo + row) * HDd + ((off - 256) >> 1);
        uint32_t dst = sb + QsO + row * 512 + (off & ~127) + ((off & 127) ^ ((row & 7) << 4));
        CP_ASYNC16(dst, src);
    }
    CP_COMMIT();

    // ---- K/V tile loader ----
#define LOAD_KV(kb_, s_) do {                                                        \
    const int _klo = (kb_) * 64;                                                     \
    _Pragma("unroll")                                                                \
    for (int _i = 0; _i < 8; _i++) {                                                 \
        int _idx = tid + 256 * _i;                                                   \
        int _row = _idx >> 5;                                                        \
        int _off = (_idx & 31) * 16;                                                 \
        const __nv_bfloat16* _src = (_off < 256)                                     \
            ? kh + ((size_t)bh * Ss + _klo + _row) * HDd + (_off >> 1)               \
            : kl + ((size_t)bh * Ss + _klo + _row) * HDd + ((_off - 256) >> 1);      \
        uint32_t _dst = sb + KsO + (s_) * 32768u + _row * 512 + (_off & ~127)        \
                        + ((_off & 127) ^ ((_row & 7) << 4));                        \
        CP_ASYNC16(_dst, _src);                                                      \
    }                                                                                \
    _Pragma("unroll")                                                                \
    for (int _i = 0; _i < 4; _i++) {                                                 \
        int _idx = tid + 256 * _i;                                                   \
        int _row = _idx >> 4;                                                        \
        int _off = (_idx & 15) * 16;                                                 \
        const __nv_bfloat16* _src = vh + ((size_t)bh * Ss + _klo + _row) * HDd + (_off >> 1); \
        uint32_t _dst = sb + VhO + (s_) * 16384u + _row * 256 + (_off & ~127)        \
                        + ((_off & 127) ^ ((_row & 7) << 4));                        \
        CP_ASYNC16(_dst, _src);                                                      \
    }                                                                                \
    _Pragma("unroll")                                                                \
    for (int _i = 0; _i < 4; _i++) {                                                 \
        int _idx = tid + 256 * _i;                                                   \
        int _row = _idx >> 4;                                                        \
        int _off = (_idx & 15) * 16;                                                 \
        const __nv_bfloat16* _src = vl + ((size_t)bh * Ss + _klo + _row) * HDd + (_off >> 1); \
        uint32_t _dst = sb + VlO + (s_) * 16384u + _row * 256 + (_off & ~127)        \
                        + ((_off & 127) ^ ((_row & 7) << 4));                        \
        CP_ASYNC16(_dst, _src);                                                      \
    }                                                                                \
    CP_COMMIT();                                                                     \
} while (0)

    LOAD_KV(0, 0);

    // per-thread fragment address components
    const int a_row = wr + (lane & 15);
    const uint32_t a_base = sb + QsO + a_row * 512;
    const uint32_t a_half = (uint32_t)((lane >> 4) * 16);
    const uint32_t a_xor = (uint32_t)((a_row & 7) * 16);

    const int b_rowk = (lane & 7) + ((lane >> 4) << 3);   // K frags (2 n-tiles)
    const uint32_t b_halfk = (uint32_t)(((lane >> 3) & 1) * 16);
    const uint32_t b_xork = (uint32_t)((lane & 7) * 16);

    const int v_row = (lane & 7) + (((lane >> 3) & 1) << 3);  // V frags (trans)
    const uint32_t v_half = (uint32_t)((lane >> 4) * 16);
    const uint32_t v_xor = (uint32_t)((lane & 7) * 16);

    float oacc[16][4];
#pragma unroll
    for (int i = 0; i < 16; i++)
#pragma unroll
        for (int q = 0; q < 4; q++) oacc[i][q] = 0.f;
    float m0 = -1e30f, m1 = -1e30f, l0 = 0.f, l1 = 0.f;

    const int row_q0 = qlo + wr + (lane >> 2);   // row for c0/c1
    const int nkb = 2 * qb + 2;

    for (int kb = 0; kb < nkb; kb++) {
        const int klo = kb * 64;
        CP_WAIT0();
        __syncthreads();
        if (kb + 1 < nkb) LOAD_KV(kb + 1, (kb + 1) & 1);

        const bool warp_skip = (klo > qlo + wr + 15);
        if (!warp_skip) {
            const uint32_t kbase = sb + KsO + (uint32_t)(kb & 1) * 32768u;
            const uint32_t vhb = sb + VhO + (uint32_t)(kb & 1) * 16384u;
            const uint32_t vlb = sb + VlO + (uint32_t)(kb & 1) * 16384u;

            float sacc[8][4];
#pragma unroll
            for (int i = 0; i < 8; i++)
#pragma unroll
                for (int q = 0; q < 4; q++) sacc[i][q] = 0.f;

            // ---- S = qhi*khi + qlo*khi + qhi*klo ----
#pragma unroll
            for (int kk = 0; kk < 8; kk++) {
                const uint32_t acol = ((uint32_t)((kk & 3) * 32) + a_half) ^ a_xor;
                const uint32_t achunk = (uint32_t)((kk >> 2) * 128);
                uint32_t ahi[4], alo[4];
                ldsm_x4(ahi, a_base + achunk + acol);
                ldsm_x4(alo, a_base + 256u + achunk + acol);
                const uint32_t bcol = ((uint32_t)((kk & 3) * 32) + b_halfk) ^ b_xork;
#pragma unroll
                for (int g = 0; g < 4; g++) {
                    uint32_t bk[4];
                    ldsm_x4(bk, kbase + (uint32_t)((g * 16 + b_rowk) * 512) + achunk + bcol);
                    mma16816(sacc[2 * g],     ahi, bk);
                    mma16816(sacc[2 * g + 1], ahi, bk + 2);
                    mma16816(sacc[2 * g],     alo, bk);
                    mma16816(sacc[2 * g + 1], alo, bk + 2);
                }
            }
#pragma unroll
            for (int kk = 0; kk < 8; kk++) {
                const uint32_t acol = ((uint32_t)((kk & 3) * 32) + a_half) ^ a_xor;
                const uint32_t achunk = (uint32_t)((kk >> 2) * 128);
                uint32_t ahi[4];
                ldsm_x4(ahi, a_base + achunk + acol);
                const uint32_t bcol = ((uint32_t)((kk & 3) * 32) + b_halfk) ^ b_xork;
#pragma unroll
                for (int g = 0; g < 4; g++) {
                    uint32_t bk[4];
                    ldsm_x4(bk, kbase + 256u + (uint32_t)((g * 16 + b_rowk) * 512) + achunk + bcol);
                    mma16816(sacc[2 * g],     ahi, bk);
                    mma16816(sacc[2 * g + 1], ahi, bk + 2);
                }
            }

            // ---- causal mask ----
            if (klo + 63 > qlo + wr) {
#pragma unroll
                for (int nt = 0; nt < 8; nt++) {
                    const int cb = klo + nt * 8 + (lane & 3) * 2;
                    if (cb     > row_q0)     sacc[nt][0] = -1e30f;
                    if (cb + 1 > row_q0)     sacc[nt][1] = -1e30f;
                    if (cb     > row_q0 + 8) sacc[nt][2] = -1e30f;
                    if (cb + 1 > row_q0 + 8) sacc[nt][3] = -1e30f;
                }
            }

            // ---- online softmax ----
            float nm0 = -1e30f, nm1 = -1e30f;
#pragma unroll
            for (int nt = 0; nt < 8; nt++) {
                nm0 = fmaxf(nm0, fmaxf(sacc[nt][0], sacc[nt][1]));
                nm1 = fmaxf(nm1, fmaxf(sacc[nt][2], sacc[nt][3]));
            }
            nm0 = fmaxf(nm0, __shfl_xor_sync(0xffffffffu, nm0, 1));
            nm0 = fmaxf(nm0, __shfl_xor_sync(0xffffffffu, nm0, 2));
            nm1 = fmaxf(nm1, __shfl_xor_sync(0xffffffffu, nm1, 1));
            nm1 = fmaxf(nm1, __shfl_xor_sync(0xffffffffu, nm1, 2));
            nm0 = fmaxf(m0, nm0);
            nm1 = fmaxf(m1, nm1);
            const float alpha0 = __expf(m0 - nm0);
            const float alpha1 = __expf(m1 - nm1);
            m0 = nm0; m1 = nm1;

            uint32_t phi[8][2], plo[8][2];
            float s0 = 0.f, s1 = 0.f;
#pragma unroll
            for (int nt = 0; nt < 8; nt++) {
                float p00 = __expf(sacc[nt][0] - m0);
                float p01 = __expf(sacc[nt][1] - m0);
                float p10 = __expf(sacc[nt][2] - m1);
                float p11 = __expf(sacc[nt][3] - m1);
                s0 += p00 + p01;
                s1 += p10 + p11;
                __nv_bfloat162 h0 = __float22bfloat162_rn(make_float2(p00, p01));
                __nv_bfloat162 h1 = __float22bfloat162_rn(make_float2(p10, p11));
                phi[nt][0] = *(uint32_t*)&h0;
                phi[nt][1] = *(uint32_t*)&h1;
                float2 hf0 = __bfloat1622float2(h0);
                float2 hf1 = __bfloat1622float2(h1);
                __nv_bfloat162 e0 = __float22bfloat162_rn(make_float2(p00 - hf0.x, p01 - hf0.y));
                __nv_bfloat162 e1 = __float22bfloat162_rn(make_float2(p10 - hf1.x, p11 - hf1.y));
                plo[nt][0] = *(uint32_t*)&e0;
                plo[nt][1] = *(uint32_t*)&e1;
            }
            s0 += __shfl_xor_sync(0xffffffffu, s0, 1);
            s0 += __shfl_xor_sync(0xffffffffu, s0, 2);
            s1 += __shfl_xor_sync(0xffffffffu, s1, 1);
            s1 += __shfl_xor_sync(0xffffffffu, s1, 2);
            l0 = l0 * alpha0 + s0;
            l1 = l1 * alpha1 + s1;
#pragma unroll
            for (int dt = 0; dt < 16; dt++) {
                oacc[dt][0] *= alpha0; oacc[dt][1] *= alpha0;
                oacc[dt][2] *= alpha1; oacc[dt][3] *= alpha1;
            }

            // ---- O += Phi*Vh + Plo*Vh + Phi*Vl ----
#pragma unroll
            for (int jt = 0; jt < 4; jt++) {
                uint32_t ah[4] = { phi[2 * jt][0], phi[2 * jt][1],
                                   phi[2 * jt + 1][0], phi[2 * jt + 1][1] };
                uint32_t al[4] = { plo[2 * jt][0], plo[2 * jt][1],
                                   plo[2 * jt + 1][0], plo[2 * jt + 1][1] };
                const uint32_t vrow = (uint32_t)((jt * 16 + v_row) * 256);
#pragma unroll
                for (int g = 0; g < 8; g++) {
                    const uint32_t colb = (uint32_t)(g * 32) + v_half;
                    const uint32_t voff = vrow + (colb & ~127u) + ((colb & 127u) ^ v_xor);
                    uint32_t bv[4];
                    ldsm_x4_t(bv, vhb + voff);
                    mma16816(oacc[2 * g],     ah, bv);
                    mma16816(oacc[2 * g + 1], ah, bv + 2);
                    mma16816(oacc[2 * g],     al, bv);
                    mma16816(oacc[2 * g + 1], al, bv + 2);
                }
#pragma unroll
                for (int g = 0; g < 8; g++) {
                    const uint32_t colb = (uint32_t)(g * 32) + v_half;
                    const uint32_t voff = vrow + (colb & ~127u) + ((colb & 127u) ^ v_xor);
                    uint32_t bv[4];
                    ldsm_x4_t(bv, vlb + voff);
                    mma16816(oacc[2 * g],     ah, bv);
                    mma16816(oacc[2 * g + 1], ah, bv + 2);
                }
            }
        }
        __syncthreads();
    }

    // ---- epilogue: normalize + write [B,S,H] ----
    const float inv0 = 1.f / l0;
    const float inv1 = 1.f / l1;
    const int col0 = h * HDd + (lane & 3) * 2;
    const size_t base0 = ((size_t)b * Ss + row_q0) * Hh + col0;
    const size_t base1 = ((size_t)b * Ss + row_q0 + 8) * Hh + col0;
#pragma unroll
    for (int dt = 0; dt < 16; dt++) {
        *(float2*)(O + base0 + dt * 8) = make_float2(oacc[dt][0] * inv0, oacc[dt][1] * inv0);
        *(float2*)(O + base1 + dt * 8) = make_float2(oacc[dt][2] * inv1, oacc[dt][3] * inv1);
    }
#undef LOAD_KV
}

// ---------------- launch ----------------
extern "C" void kernel_launch(void* const* d_in, const int* in_sizes, int n_in,
                              void* d_out, int out_size)
{
    (void)in_sizes; (void)n_in; (void)out_size;
    const float* hs = (const float*)d_in[0];
    const float* qw = (const float*)d_in[1];
    const float* kw = (const float*)d_in[2];
    const float* vw = (const float*)d_in[3];
    const float* ow = (const float*)d_in[4];
    float* out = (float*)d_out;

    float *qbuf, *kbuf, *vbuf, *obuf;
    __nv_bfloat16 *a3, *w3, *qh, *ql, *kh, *kl, *vh, *vl;
    cudaGetSymbolAddress((void**)&qbuf, g_q);
    cudaGetSymbolAddress((void**)&kbuf, g_k);
    cudaGetSymbolAddress((void**)&vbuf, g_v);
    cudaGetSymbolAddress((void**)&obuf, g_o);
    cudaGetSymbolAddress((void**)&a3, g_a3);
    cudaGetSymbolAddress((void**)&w3, g_w3);
    cudaGetSymbolAddress((void**)&qh, g_qh);
    cudaGetSymbolAddress((void**)&ql, g_ql);
    cudaGetSymbolAddress((void**)&kh, g_kh);
    cudaGetSymbolAddress((void**)&kl, g_kl);
    cudaGetSymbolAddress((void**)&vh, g_vh);
    cudaGetSymbolAddress((void**)&vl, g_vl);

    const int gemm_smem = 65536;
    cudaFuncSetAttribute(gemm_mma<0>, cudaFuncAttributeMaxDynamicSharedMemorySize, gemm_smem);
    cudaFuncSetAttribute(gemm_mma<1>, cudaFuncAttributeMaxDynamicSharedMemorySize, gemm_smem);
    cudaFuncSetAttribute(flash_mma, cudaFuncAttributeMaxDynamicSharedMemorySize, FLASH_SMEM);

    const dim3 gGemm(Hh / 128, Mm / 128);
    const int actN = Mm * Hh;
    const int wN = Hh * Hh;
    const int qkvN = Bb * NHh * Ss * HDd;

    split_kernel<<<(actN + 255) / 256, 256>>>(hs, a3, actN, 0);

    split_kernel<<<(wN + 255) / 256, 256>>>(qw, w3, wN, 1);
    gemm_mma<1><<<gGemm, 256, gemm_smem>>>(a3, w3, qbuf);
    split_kernel<<<(wN + 255) / 256, 256>>>(kw, w3, wN, 1);
    gemm_mma<1><<<gGemm, 256, gemm_smem>>>(a3, w3, kbuf);
    split_kernel<<<(wN + 255) / 256, 256>>>(vw, w3, wN, 1);
    gemm_mma<1><<<gGemm, 256, gemm_smem>>>(a3, w3, vbuf);

    rope_tables_kernel<<<(Ss * 64 + 255) / 256, 256>>>();
    rope_split_kernel<<<(Bb * NHh * Ss * 64 + 255) / 256, 256>>>(qbuf, kbuf, qh, ql, kh, kl);
    split_pair_kernel<<<(qkvN + 255) / 256, 256>>>(vbuf, vh, vl, qkvN);

    flash_mma<<<dim3(Ss / 128, Bb * NHh), 256, FLASH_SMEM>>>(qh, ql, kh, kl, vh, vl, obuf);

    split_kernel<<<(actN + 255) / 256, 256>>>(obuf, a3, actN, 0);
    split_kernel<<<(wN + 255) / 256, 256>>>(ow, w3, wN, 1);
    gemm_mma<0><<<gGemm, 256, gemm_smem>>>(a3, w3, out);
}

// round 5
// speedup vs baseline: 3.5672x; 1.0077x over previous
#include <cuda_runtime.h>
#include <cuda_bf16.h>
#include <math.h>
#include <stdint.h>

#define Bb 2
#define Ss 2048
#define Hh 2048
#define NHh 16
#define HDd 128
#define Mm (Bb*Ss)
#define K3 (3*Hh)          // 6144 (bf16x3 split along K)
#define KC 64
#define NCHUNK (K3/KC)     // 96

// ---------------- scratch ----------------
__device__ float g_q[(size_t)Bb*NHh*Ss*HDd];
__device__ float g_k[(size_t)Bb*NHh*Ss*HDd];
__device__ float g_v[(size_t)Bb*NHh*Ss*HDd];
__device__ float g_o[(size_t)Bb*Ss*Hh];
__device__ float g_cos[Ss*64];
__device__ float g_sin[Ss*64];
__device__ __nv_bfloat16 g_a3[(size_t)Mm*K3];
__device__ __nv_bfloat16 g_w3q[(size_t)Hh*K3];
__device__ __nv_bfloat16 g_w3k[(size_t)Hh*K3];
__device__ __nv_bfloat16 g_w3v[(size_t)Hh*K3];
// flash bf16 operands (hi/lo split)
__device__ __nv_bfloat16 g_qh[(size_t)Bb*NHh*Ss*HDd];
__device__ __nv_bfloat16 g_ql[(size_t)Bb*NHh*Ss*HDd];
__device__ __nv_bfloat16 g_kh[(size_t)Bb*NHh*Ss*HDd];
__device__ __nv_bfloat16 g_kl[(size_t)Bb*NHh*Ss*HDd];
__device__ __nv_bfloat16 g_vh[(size_t)Bb*NHh*Ss*HDd];
__device__ __nv_bfloat16 g_vl[(size_t)Bb*NHh*Ss*HDd];

// ---------------- PTX helpers ----------------
__device__ __forceinline__ uint32_t smem_u32(const void* p) {
    uint32_t a;
    asm("{ .reg .u64 t; cvta.to.shared.u64 t, %1; cvt.u32.u64 %0, t; }" : "=r"(a) : "l"(p));
    return a;
}
#define CP_ASYNC16(sa, gp) \
    asm volatile("cp.async.cg.shared.global [%0], [%1], 16;" :: "r"(sa), "l"(gp) : "memory")
#define CP_COMMIT() asm volatile("cp.async.commit_group;" ::: "memory")
#define CP_WAIT0()  asm volatile("cp.async.wait_group 0;" ::: "memory")
#define CP_WAIT1()  asm volatile("cp.async.wait_group 1;" ::: "memory")

__device__ __forceinline__ void ldsm_x4(uint32_t* r, uint32_t addr) {
    asm volatile("ldmatrix.sync.aligned.m8n8.x4.shared.b16 {%0,%1,%2,%3}, [%4];"
        : "=r"(r[0]), "=r"(r[1]), "=r"(r[2]), "=r"(r[3]) : "r"(addr));
}
__device__ __forceinline__ void ldsm_x4_t(uint32_t* r, uint32_t addr) {
    asm volatile("ldmatrix.sync.aligned.m8n8.x4.trans.shared.b16 {%0,%1,%2,%3}, [%4];"
        : "=r"(r[0]), "=r"(r[1]), "=r"(r[2]), "=r"(r[3]) : "r"(addr));
}
__device__ __forceinline__ void mma16816(float* d, const uint32_t* a, const uint32_t* b) {
    asm volatile("mma.sync.aligned.m16n8k16.row.col.f32.bf16.bf16.f32 "
        "{%0,%1,%2,%3}, {%4,%5,%6,%7}, {%8,%9}, {%0,%1,%2,%3};"
        : "+f"(d[0]), "+f"(d[1]), "+f"(d[2]), "+f"(d[3])
        : "r"(a[0]), "r"(a[1]), "r"(a[2]), "r"(a[3]), "r"(b[0]), "r"(b[1]));
}
#define SWZ(off) ((off) ^ (((off) >> 3) & 0x70))

// ---------------- split fp32 -> bf16x3 along K (for projections) ----------------
__global__ void split_kernel(const float* __restrict__ X, __nv_bfloat16* __restrict__ Y,
                             int total, int order)
{
    int idx = blockIdx.x * blockDim.x + threadIdx.x;
    if (idx >= total) return;
    const int r = idx >> 11;
    const int k = idx & 2047;
    const float x = X[idx];
    const __nv_bfloat16 hi = __float2bfloat16(x);
    const __nv_bfloat16 lo = __float2bfloat16(x - __bfloat162float(hi));
    const size_t base = (size_t)r * K3 + k;
    Y[base] = hi;
    Y[base + Hh]     = order ? hi : lo;
    Y[base + 2 * Hh] = order ? lo : hi;
}

// ---------------- plain hi/lo pair split (for V) ----------------
__global__ void split_pair_kernel(const float* __restrict__ X,
                                  __nv_bfloat16* __restrict__ Xh,
                                  __nv_bfloat16* __restrict__ Xl, int n)
{
    int idx = blockIdx.x * blockDim.x + threadIdx.x;
    if (idx >= n) return;
    float x = X[idx];
    __nv_bfloat16 hi = __float2bfloat16(x);
    Xh[idx] = hi;
    Xl[idx] = __float2bfloat16(x - __bfloat162float(hi));
}

// ---------------- HMMA GEMM v2: CTA 128x128, 4 warps (64x64 each), 3-stage -----
// C[M,N] = A'[M,3K] * B'[N,3K]^T.  MODE 0: row-major [M,N]; MODE 1: head scatter.
template <int MODE>
__global__ __launch_bounds__(128, 2) void gemm_mma(const __nv_bfloat16* __restrict__ A,
                                                   const __nv_bfloat16* __restrict__ Bw,
                                                   float* __restrict__ C)
{
    extern __shared__ char smem[];
    const uint32_t sb = smem_u32(smem);
    const int tid = threadIdx.x;
    const int wid = tid >> 5;
    const int lane = tid & 31;
    const int n0 = blockIdx.x * 128;
    const int m0 = blockIdx.y * 128;
    const int wm = wid & 1;      // 64-row half
    const int wn = wid >> 1;     // 64-col half

    float acc[4][8][4];
#pragma unroll
    for (int mi = 0; mi < 4; mi++)
#pragma unroll
        for (int ni = 0; ni < 8; ni++)
#pragma unroll
            for (int q = 0; q < 4; q++) acc[mi][ni][q] = 0.f;

    // stage s: A at s*32768, B at s*32768+16384 (128 rows x 128B each)
#define LOAD_STAGE(cidx, st) do {                                                   \
    const int _k0 = (cidx) * KC;                                                    \
    const uint32_t _ab = sb + (uint32_t)(st) * 32768u;                              \
    _Pragma("unroll")                                                               \
    for (int _i = 0; _i < 8; _i++) {                                                \
        int _idx = tid + 128 * _i;                                                  \
        int _r = _idx >> 3;                                                         \
        int _c = (_idx & 7) * 16;                                                   \
        CP_ASYNC16(_ab + SWZ(_r * 128 + _c),                                        \
                   A + (size_t)(m0 + _r) * K3 + _k0 + (_c >> 1));                   \
    }                                                                               \
    _Pragma("unroll")                                                               \
    for (int _i = 0; _i < 8; _i++) {                                                \
        int _idx = tid + 128 * _i;                                                  \
        int _r = _idx >> 3;                                                         \
        int _c = (_idx & 7) * 16;                                                   \
        CP_ASYNC16(_ab + 16384u + SWZ(_r * 128 + _c),                               \
                   Bw + (size_t)(n0 + _r) * K3 + _k0 + (_c >> 1));                  \
    }                                                                               \
    CP_COMMIT();                                                                    \
} while (0)

    // ldmatrix address components
    const uint32_t a_half = (uint32_t)((lane >> 4) * 16);
    const uint32_t a_xor = (uint32_t)((lane & 7) * 16);
    uint32_t aRow[4];
#pragma unroll
    for (int mi = 0; mi < 4; mi++)
        aRow[mi] = (uint32_t)((wm * 64 + mi * 16 + (lane & 15)) * 128);

    const int b_lrow = (lane & 7) + ((lane >> 4) << 3);
    const uint32_t b_half = (uint32_t)(((lane >> 3) & 1) * 16);
    const uint32_t b_xor = (uint32_t)((lane & 7) * 16);
    uint32_t bRow[4];
#pragma unroll
    for (int nt = 0; nt < 4; nt++)
        bRow[nt] = (uint32_t)((wn * 64 + nt * 16 + b_lrow) * 128);

    LOAD_STAGE(0, 0);
    LOAD_STAGE(1, 1);

    int st = 0;
    for (int c = 0; c < NCHUNK; c++) {
        if (c + 1 < NCHUNK) CP_WAIT1(); else CP_WAIT0();
        __syncthreads();
        if (c + 2 < NCHUNK) {
            int st2 = st + 2; if (st2 >= 3) st2 -= 3;
            LOAD_STAGE(c + 2, st2);
        }

        const uint32_t abase = sb + (uint32_t)st * 32768u;
        const uint32_t bbase = abase + 16384u;
#pragma unroll
        for (int kk = 0; kk < 4; kk++) {
            const uint32_t acol = ((uint32_t)(kk * 32) + a_half) ^ a_xor;
            const uint32_t bcol = ((uint32_t)(kk * 32) + b_half) ^ b_xor;
            uint32_t afr[4][4], bfr[4][4];
#pragma unroll
            for (int mi = 0; mi < 4; mi++)
                ldsm_x4(afr[mi], abase + aRow[mi] + acol);
#pragma unroll
            for (int nt = 0; nt < 4; nt++)
                ldsm_x4(bfr[nt], bbase + bRow[nt] + bcol);
#pragma unroll
            for (int mi = 0; mi < 4; mi++)
#pragma unroll
                for (int nt = 0; nt < 4; nt++) {
                    mma16816(acc[mi][2 * nt],     afr[mi], bfr[nt]);
                    mma16816(acc[mi][2 * nt + 1], afr[mi], bfr[nt] + 2);
                }
        }
        if (++st == 3) st = 0;
    }

    // epilogue
    const int er = lane >> 2;
    const int ec = (lane & 3) * 2;
#pragma unroll
    for (int mi = 0; mi < 4; mi++) {
#pragma unroll
        for (int ni = 0; ni < 8; ni++) {
            const int m = m0 + wm * 64 + mi * 16 + er;
            const int n = n0 + wn * 64 + ni * 8 + ec;
            float* dst0;
            float* dst1;
            if (MODE == 0) {
                dst0 = C + (size_t)m * Hh + n;
                dst1 = C + (size_t)(m + 8) * Hh + n;
            } else {
                const int b_ = m >> 11;
                const int s_ = m & (Ss - 1);
                const int h_ = n >> 7;
                const int d_ = n & (HDd - 1);
                dst0 = C + (((size_t)b_ * NHh + h_) * Ss + s_) * HDd + d_;
                dst1 = dst0 + 8 * HDd;
            }
            *(float2*)dst0 = make_float2(acc[mi][ni][0], acc[mi][ni][1]);
            *(float2*)dst1 = make_float2(acc[mi][ni][2], acc[mi][ni][3]);
        }
    }
#undef LOAD_STAGE
}

// ---------------- RoPE tables ----------------
__global__ void rope_tables_kernel()
{
    int idx = blockIdx.x * blockDim.x + threadIdx.x;
    if (idx >= Ss * 64) return;
    int s = idx >> 6;
    int d = idx & 63;
    float invf = (float)pow(10000.0, -(double)d * (1.0 / 64.0));
    float ang = (float)s * invf;
    float c, sn;
    sincosf(ang, &sn, &c);
    g_cos[idx] = c;
    g_sin[idx] = sn;
}

// ---------------- RoPE apply + bf16 hi/lo split (Q scaled by 1/sqrt(HD)) --------
__global__ void rope_split_kernel(const float* __restrict__ q, const float* __restrict__ k,
                                  __nv_bfloat16* __restrict__ qh, __nv_bfloat16* __restrict__ ql,
                                  __nv_bfloat16* __restrict__ kh, __nv_bfloat16* __restrict__ kl)
{
    int idx = blockIdx.x * blockDim.x + threadIdx.x;
    if (idx >= Bb * NHh * Ss * 64) return;
    const int d = idx & 63;
    const int s = (idx >> 6) & (Ss - 1);
    const int bh = idx >> 17;
    const int t = (s << 6) + d;
    const float c = g_cos[t];
    const float sn = g_sin[t];
    const float rscale = 0.08838834764831845f;
    const size_t base = ((size_t)bh * Ss + s) * HDd + d;

    float q1 = q[base], q2 = q[base + 64];
    float r1 = (q1 * c - q2 * sn) * rscale;
    float r2 = (q2 * c + q1 * sn) * rscale;
    __nv_bfloat16 h1 = __float2bfloat16(r1);
    __nv_bfloat16 h2 = __float2bfloat16(r2);
    qh[base] = h1; qh[base + 64] = h2;
    ql[base] = __float2bfloat16(r1 - __bfloat162float(h1));
    ql[base + 64] = __float2bfloat16(r2 - __bfloat162float(h2));

    float k1 = k[base], k2 = k[base + 64];
    float s1 = k1 * c - k2 * sn;
    float s2 = k2 * c + k1 * sn;
    __nv_bfloat16 g1 = __float2bfloat16(s1);
    __nv_bfloat16 g2 = __float2bfloat16(s2);
    kh[base] = g1; kh[base + 64] = g2;
    kl[base] = __float2bfloat16(s1 - __bfloat162float(g1));
    kl[base + 64] = __float2bfloat16(s2 - __bfloat162float(g2));
}

// ---------------- HMMA causal flash attention, BM=128, BN=64 ----------------
#define QsO 0u
#define KsO 65536u
#define VhO 131072u
#define VlO 163840u
#define FLASH_SMEM 196608

__global__ __launch_bounds__(256, 1) void flash_mma(
    const __nv_bfloat16* __restrict__ qh, const __nv_bfloat16* __restrict__ ql,
    const __nv_bfloat16* __restrict__ kh, const __nv_bfloat16* __restrict__ kl,
    const __nv_bfloat16* __restrict__ vh, const __nv_bfloat16* __restrict__ vl,
    float* __restrict__ O)
{
    extern __shared__ char smem[];
    const uint32_t sb = smem_u32(smem);
    const int tid = threadIdx.x;
    const int lane = tid & 31;
    const int w = tid >> 5;
    const int qb = (gridDim.x - 1) - blockIdx.x;
    const int bh = blockIdx.y;
    const int b = bh >> 4, h = bh & 15;
    const int qlo = qb * 128;
    const int wr = w * 16;

#pragma unroll
    for (int i = 0; i < 16; i++) {
        int idx = tid + 256 * i;
        int row = idx >> 5;
        int off = (idx & 31) * 16;
        const __nv_bfloat16* src = (off < 256)
            ? qh + ((size_t)bh * Ss + qlo + row) * HDd + (off >> 1)
            : ql + ((size_t)bh * Ss + qlo + row) * HDd + ((off - 256) >> 1);
        uint32_t dst = sb + QsO + row * 512 + (off & ~127) + ((off & 127) ^ ((row & 7) << 4));
        CP_ASYNC16(dst, src);
    }
    CP_COMMIT();

#define LOAD_KV(kb_, s_) do {                                                        \
    const int _klo = (kb_) * 64;                                                     \
    _Pragma("unroll")                                                                \
    for (int _i = 0; _i < 8; _i++) {                                                 \
        int _idx = tid + 256 * _i;                                                   \
        int _row = _idx >> 5;                                                        \
        int _off = (_idx & 31) * 16;                                                 \
        const __nv_bfloat16* _src = (_off < 256)                                     \
            ? kh + ((size_t)bh * Ss + _klo + _row) * HDd + (_off >> 1)               \
            : kl + ((size_t)bh * Ss + _klo + _row) * HDd + ((_off - 256) >> 1);      \
        uint32_t _dst = sb + KsO + (s_) * 32768u + _row * 512 + (_off & ~127)        \
                        + ((_off & 127) ^ ((_row & 7) << 4));                        \
        CP_ASYNC16(_dst, _src);                                                      \
    }                                                                                \
    _Pragma("unroll")                                                                \
    for (int _i = 0; _i < 4; _i++) {                                                 \
        int _idx = tid + 256 * _i;                                                   \
        int _row = _idx >> 4;                                                        \
        int _off = (_idx & 15) * 16;                                                 \
        const __nv_bfloat16* _src = vh + ((size_t)bh * Ss + _klo + _row) * HDd + (_off >> 1); \
        uint32_t _dst = sb + VhO + (s_) * 16384u + _row * 256 + (_off & ~127)        \
                        + ((_off & 127) ^ ((_row & 7) << 4));                        \
        CP_ASYNC16(_dst, _src);                                                      \
    }                                                                                \
    _Pragma("unroll")                                                                \
    for (int _i = 0; _i < 4; _i++) {                                                 \
        int _idx = tid + 256 * _i;                                                   \
        int _row = _idx >> 4;                                                        \
        int _off = (_idx & 15) * 16;                                                 \
        const __nv_bfloat16* _src = vl + ((size_t)bh * Ss + _klo + _row) * HDd + (_off >> 1); \
        uint32_t _dst = sb + VlO + (s_) * 16384u + _row * 256 + (_off & ~127)        \
                        + ((_off & 127) ^ ((_row & 7) << 4));                        \
        CP_ASYNC16(_dst, _src);                                                      \
    }                                                                                \
    CP_COMMIT();                                                                     \
} while (0)

    LOAD_KV(0, 0);

    const int a_row = wr + (lane & 15);
    const uint32_t a_base = sb + QsO + a_row * 512;
    const uint32_t a_half = (uint32_t)((lane >> 4) * 16);
    const uint32_t a_xor = (uint32_t)((a_row & 7) * 16);

    const int b_rowk = (lane & 7) + ((lane >> 4) << 3);
    const uint32_t b_halfk = (uint32_t)(((lane >> 3) & 1) * 16);
    const uint32_t b_xork = (uint32_t)((lane & 7) * 16);

    const int v_row = (lane & 7) + (((lane >> 3) & 1) << 3);
    const uint32_t v_half = (uint32_t)((lane >> 4) * 16);
    const uint32_t v_xor = (uint32_t)((lane & 7) * 16);

    float oacc[16][4];
#pragma unroll
    for (int i = 0; i < 16; i++)
#pragma unroll
        for (int q = 0; q < 4; q++) oacc[i][q] = 0.f;
    float m0 = -1e30f, m1 = -1e30f, l0 = 0.f, l1 = 0.f;

    const int row_q0 = qlo + wr + (lane >> 2);
    const int nkb = 2 * qb + 2;

    for (int kb = 0; kb < nkb; kb++) {
        const int klo = kb * 64;
        CP_WAIT0();
        __syncthreads();
        if (kb + 1 < nkb) LOAD_KV(kb + 1, (kb + 1) & 1);

        const bool warp_skip = (klo > qlo + wr + 15);
        if (!warp_skip) {
            const uint32_t kbase = sb + KsO + (uint32_t)(kb & 1) * 32768u;
            const uint32_t vhb = sb + VhO + (uint32_t)(kb & 1) * 16384u;
            const uint32_t vlb = sb + VlO + (uint32_t)(kb & 1) * 16384u;

            float sacc[8][4];
#pragma unroll
            for (int i = 0; i < 8; i++)
#pragma unroll
                for (int q = 0; q < 4; q++) sacc[i][q] = 0.f;

#pragma unroll
            for (int kk = 0; kk < 8; kk++) {
                const uint32_t acol = ((uint32_t)((kk & 3) * 32) + a_half) ^ a_xor;
                const uint32_t achunk = (uint32_t)((kk >> 2) * 128);
                uint32_t ahi[4], alo[4];
                ldsm_x4(ahi, a_base + achunk + acol);
                ldsm_x4(alo, a_base + 256u + achunk + acol);
                const uint32_t bcol = ((uint32_t)((kk & 3) * 32) + b_halfk) ^ b_xork;
#pragma unroll
                for (int g = 0; g < 4; g++) {
                    uint32_t bk[4];
                    ldsm_x4(bk, kbase + (uint32_t)((g * 16 + b_rowk) * 512) + achunk + bcol);
                    mma16816(sacc[2 * g],     ahi, bk);
                    mma16816(sacc[2 * g + 1], ahi, bk + 2);
                    mma16816(sacc[2 * g],     alo, bk);
                    mma16816(sacc[2 * g + 1], alo, bk + 2);
                }
            }
#pragma unroll
            for (int kk = 0; kk < 8; kk++) {
                const uint32_t acol = ((uint32_t)((kk & 3) * 32) + a_half) ^ a_xor;
                const uint32_t achunk = (uint32_t)((kk >> 2) * 128);
                uint32_t ahi[4];
                ldsm_x4(ahi, a_base + achunk + acol);
                const uint32_t bcol = ((uint32_t)((kk & 3) * 32) + b_halfk) ^ b_xork;
#pragma unroll
                for (int g = 0; g < 4; g++) {
                    uint32_t bk[4];
                    ldsm_x4(bk, kbase + 256u + (uint32_t)((g * 16 + b_rowk) * 512) + achunk + bcol);
                    mma16816(sacc[2 * g],     ahi, bk);
                    mma16816(sacc[2 * g + 1], ahi, bk + 2);
                }
            }

            if (klo + 63 > qlo + wr) {
#pragma unroll
                for (int nt = 0; nt < 8; nt++) {
                    const int cb = klo + nt * 8 + (lane & 3) * 2;
                    if (cb     > row_q0)     sacc[nt][0] = -1e30f;
                    if (cb + 1 > row_q0)     sacc[nt][1] = -1e30f;
                    if (cb     > row_q0 + 8) sacc[nt][2] = -1e30f;
                    if (cb + 1 > row_q0 + 8) sacc[nt][3] = -1e30f;
                }
            }

            float nm0 = -1e30f, nm1 = -1e30f;
#pragma unroll
            for (int nt = 0; nt < 8; nt++) {
                nm0 = fmaxf(nm0, fmaxf(sacc[nt][0], sacc[nt][1]));
                nm1 = fmaxf(nm1, fmaxf(sacc[nt][2], sacc[nt][3]));
            }
            nm0 = fmaxf(nm0, __shfl_xor_sync(0xffffffffu, nm0, 1));
            nm0 = fmaxf(nm0, __shfl_xor_sync(0xffffffffu, nm0, 2));
            nm1 = fmaxf(nm1, __shfl_xor_sync(0xffffffffu, nm1, 1));
            nm1 = fmaxf(nm1, __shfl_xor_sync(0xffffffffu, nm1, 2));
            nm0 = fmaxf(m0, nm0);
            nm1 = fmaxf(m1, nm1);
            const float alpha0 = __expf(m0 - nm0);
            const float alpha1 = __expf(m1 - nm1);
            m0 = nm0; m1 = nm1;

            uint32_t phi[8][2], plo[8][2];
            float s0 = 0.f, s1 = 0.f;
#pragma unroll
            for (int nt = 0; nt < 8; nt++) {
                float p00 = __expf(sacc[nt][0] - m0);
                float p01 = __expf(sacc[nt][1] - m0);
                float p10 = __expf(sacc[nt][2] - m1);
                float p11 = __expf(sacc[nt][3] - m1);
                s0 += p00 + p01;
                s1 += p10 + p11;
                __nv_bfloat162 h0 = __float22bfloat162_rn(make_float2(p00, p01));
                __nv_bfloat162 h1 = __float22bfloat162_rn(make_float2(p10, p11));
                phi[nt][0] = *(uint32_t*)&h0;
                phi[nt][1] = *(uint32_t*)&h1;
                float2 hf0 = __bfloat1622float2(h0);
                float2 hf1 = __bfloat1622float2(h1);
                __nv_bfloat162 e0 = __float22bfloat162_rn(make_float2(p00 - hf0.x, p01 - hf0.y));
                __nv_bfloat162 e1 = __float22bfloat162_rn(make_float2(p10 - hf1.x, p11 - hf1.y));
                plo[nt][0] = *(uint32_t*)&e0;
                plo[nt][1] = *(uint32_t*)&e1;
            }
            s0 += __shfl_xor_sync(0xffffffffu, s0, 1);
            s0 += __shfl_xor_sync(0xffffffffu, s0, 2);
            s1 += __shfl_xor_sync(0xffffffffu, s1, 1);
            s1 += __shfl_xor_sync(0xffffffffu, s1, 2);
            l0 = l0 * alpha0 + s0;
            l1 = l1 * alpha1 + s1;
#pragma unroll
            for (int dt = 0; dt < 16; dt++) {
                oacc[dt][0] *= alpha0; oacc[dt][1] *= alpha0;
                oacc[dt][2] *= alpha1; oacc[dt][3] *= alpha1;
            }

#pragma unroll
            for (int jt = 0; jt < 4; jt++) {
                uint32_t ah[4] = { phi[2 * jt][0], phi[2 * jt][1],
                                   phi[2 * jt + 1][0], phi[2 * jt + 1][1] };
                uint32_t al[4] = { plo[2 * jt][0], plo[2 * jt][1],
                                   plo[2 * jt + 1][0], plo[2 * jt + 1][1] };
                const uint32_t vrow = (uint32_t)((jt * 16 + v_row) * 256);
#pragma unroll
                for (int g = 0; g < 8; g++) {
                    const uint32_t colb = (uint32_t)(g * 32) + v_half;
                    const uint32_t voff = vrow + (colb & ~127u) + ((colb & 127u) ^ v_xor);
                    uint32_t bv[4];
                    ldsm_x4_t(bv, vhb + voff);
                    mma16816(oacc[2 * g],     ah, bv);
                    mma16816(oacc[2 * g + 1], ah, bv + 2);
                    mma16816(oacc[2 * g],     al, bv);
                    mma16816(oacc[2 * g + 1], al, bv + 2);
                }
#pragma unroll
                for (int g = 0; g < 8; g++) {
                    const uint32_t colb = (uint32_t)(g * 32) + v_half;
                    const uint32_t voff = vrow + (colb & ~127u) + ((colb & 127u) ^ v_xor);
                    uint32_t bv[4];
                    ldsm_x4_t(bv, vlb + voff);
                    mma16816(oacc[2 * g],     ah, bv);
                    mma16816(oacc[2 * g + 1], ah, bv + 2);
                }
            }
        }
        __syncthreads();
    }

    const float inv0 = 1.f / l0;
    const float inv1 = 1.f / l1;
    const int col0 = h * HDd + (lane & 3) * 2;
    const size_t base0 = ((size_t)b * Ss + row_q0) * Hh + col0;
    const size_t base1 = ((size_t)b * Ss + row_q0 + 8) * Hh + col0;
#pragma unroll
    for (int dt = 0; dt < 16; dt++) {
        *(float2*)(O + base0 + dt * 8) = make_float2(oacc[dt][0] * inv0, oacc[dt][1] * inv0);
        *(float2*)(O + base1 + dt * 8) = make_float2(oacc[dt][2] * inv1, oacc[dt][3] * inv1);
    }
#undef LOAD_KV
}

// ---------------- launch ----------------
extern "C" void kernel_launch(void* const* d_in, const int* in_sizes, int n_in,
                              void* d_out, int out_size)
{
    (void)in_sizes; (void)n_in; (void)out_size;
    const float* hs = (const float*)d_in[0];
    const float* qw = (const float*)d_in[1];
    const float* kw = (const float*)d_in[2];
    const float* vw = (const float*)d_in[3];
    const float* ow = (const float*)d_in[4];
    float* out = (float*)d_out;

    float *qbuf, *kbuf, *vbuf, *obuf;
    __nv_bfloat16 *a3, *w3q, *w3k, *w3v, *qh, *ql, *kh, *kl, *vh, *vl;
    cudaGetSymbolAddress((void**)&qbuf, g_q);
    cudaGetSymbolAddress((void**)&kbuf, g_k);
    cudaGetSymbolAddress((void**)&vbuf, g_v);
    cudaGetSymbolAddress((void**)&obuf, g_o);
    cudaGetSymbolAddress((void**)&a3, g_a3);
    cudaGetSymbolAddress((void**)&w3q, g_w3q);
    cudaGetSymbolAddress((void**)&w3k, g_w3k);
    cudaGetSymbolAddress((void**)&w3v, g_w3v);
    cudaGetSymbolAddress((void**)&qh, g_qh);
    cudaGetSymbolAddress((void**)&ql, g_ql);
    cudaGetSymbolAddress((void**)&kh, g_kh);
    cudaGetSymbolAddress((void**)&kl, g_kl);
    cudaGetSymbolAddress((void**)&vh, g_vh);
    cudaGetSymbolAddress((void**)&vl, g_vl);

    const int gemm_smem = 98304;  // 3 stages x 32KB
    cudaFuncSetAttribute(gemm_mma<0>, cudaFuncAttributeMaxDynamicSharedMemorySize, gemm_smem);
    cudaFuncSetAttribute(gemm_mma<1>, cudaFuncAttributeMaxDynamicSharedMemorySize, gemm_smem);
    cudaFuncSetAttribute(flash_mma, cudaFuncAttributeMaxDynamicSharedMemorySize, FLASH_SMEM);

    const dim3 gGemm(Hh / 128, Mm / 128);  // (16, 32)
    const int actN = Mm * Hh;
    const int wN = Hh * Hh;
    const int qkvN = Bb * NHh * Ss * HDd;

    // all splits up front; GEMMs back-to-back
    split_kernel<<<(actN + 255) / 256, 256>>>(hs, a3, actN, 0);
    split_kernel<<<(wN + 255) / 256, 256>>>(qw, w3q, wN, 1);
    split_kernel<<<(wN + 255) / 256, 256>>>(kw, w3k, wN, 1);
    split_kernel<<<(wN + 255) / 256, 256>>>(vw, w3v, wN, 1);
    rope_tables_kernel<<<(Ss * 64 + 255) / 256, 256>>>();

    gemm_mma<1><<<gGemm, 128, gemm_smem>>>(a3, w3q, qbuf);
    gemm_mma<1><<<gGemm, 128, gemm_smem>>>(a3, w3k, kbuf);
    gemm_mma<1><<<gGemm, 128, gemm_smem>>>(a3, w3v, vbuf);

    rope_split_kernel<<<(Bb * NHh * Ss * 64 + 255) / 256, 256>>>(qbuf, kbuf, qh, ql, kh, kl);
    split_pair_kernel<<<(qkvN + 255) / 256, 256>>>(vbuf, vh, vl, qkvN);

    flash_mma<<<dim3(Ss / 128, Bb * NHh), 256, FLASH_SMEM>>>(qh, ql, kh, kl, vh, vl, obuf);

    split_kernel<<<(actN + 255) / 256, 256>>>(obuf, a3, actN, 0);
    split_kernel<<<(wN + 255) / 256, 256>>>(ow, w3q, wN, 1);
    gemm_mma<0><<<gGemm, 128, gemm_smem>>>(a3, w3q, out);
}